// round 11
// baseline (speedup 1.0000x reference)
#include <cuda_runtime.h>
#include <cstdint>

#define T_STEPS 256
#define BATCH   128
#define DIN     1024
#define HID     1024
#define NGATE   4096  // 4*HID
#define NBLK    128

// Scratch (device globals; no allocation allowed in kernel_launch).
__device__ float g_xr[(size_t)T_STEPS * BATCH * DIN];    // x, tf32-rounded, row-major (128 MB)
__device__ float g_WxF[(size_t)NBLK * 32768];            // Wx frags, per-block Bfrag layout (16 MB)
__device__ float g_h[2][BATCH * HID];                    // double-buffered hidden state
__device__ float g_c[BATCH * HID];                       // cell state
__device__ unsigned g_cnt;                               // barrier arrive counter
__device__ volatile unsigned g_gen;                      // barrier generation

// ---------------- helpers ----------------

__device__ __forceinline__ float f2tf32(float x) {
    uint32_t u;
    asm("cvt.rna.tf32.f32 %0, %1;" : "=r"(u) : "f"(x));
    return __uint_as_float(u);
}

__device__ __forceinline__ void mma_tf32(float c[4], const uint32_t a[4], const uint32_t b[2]) {
    asm volatile(
        "mma.sync.aligned.m16n8k8.row.col.f32.tf32.tf32.f32 "
        "{%0,%1,%2,%3}, {%4,%5,%6,%7}, {%8,%9}, {%0,%1,%2,%3};"
        : "+f"(c[0]), "+f"(c[1]), "+f"(c[2]), "+f"(c[3])
        : "r"(a[0]), "r"(a[1]), "r"(a[2]), "r"(a[3]), "r"(b[0]), "r"(b[1]));
}

__device__ __forceinline__ void cp_async16(uint32_t dst_smem, const void* src) {
    asm volatile("cp.async.ca.shared.global [%0], [%1], 16;" :: "r"(dst_smem), "l"(src));
}

__device__ __forceinline__ float sigmoidf_fast(float x) {
    x = fminf(fmaxf(x, -30.f), 30.f);
    return __fdividef(1.f, 1.f + __expf(-x));
}

__device__ __forceinline__ float tanhf_fast(float x) {
    x = fminf(fmaxf(x, -15.f), 15.f);
    float e = __expf(2.f * x);
    return __fdividef(e - 1.f, e + 1.f);
}

// Software grid barrier (R9-proven atomic-counter version).
__device__ __forceinline__ void grid_sync(unsigned step) {
    __syncthreads();
    if (threadIdx.x == 0) {
        __threadfence();
        unsigned a = atomicAdd(&g_cnt, 1u);
        if (a == gridDim.x - 1) {
            g_cnt = 0;
            __threadfence();
            g_gen = step + 1;
        } else {
            while (g_gen < step + 1) __nanosleep(32);
        }
        __threadfence();
    }
    __syncthreads();
}

// ---------------- init state + barrier ----------------

__global__ void init_state(const float* __restrict__ csh) {
    int idx = blockIdx.x * blockDim.x + threadIdx.x;
    if (idx == 0) { g_cnt = 0; g_gen = 0; }
    if (idx < BATCH * HID) {
        int b = idx / HID, j = idx % HID;
        g_c[idx]    = csh[b * 2 * HID + j];          // cell first
        g_h[0][idx] = csh[b * 2 * HID + HID + j];    // hidden second
    }
}

// ---------------- prep: tf32-round x; Wx -> per-block fragment layout ----

__global__ void prep_xr(const float* __restrict__ x) {
    size_t i = (size_t)blockIdx.x * 256 + threadIdx.x;  // float4 index
    float4 v = ((const float4*)x)[i];
    v.x = f2tf32(v.x); v.y = f2tf32(v.y); v.z = f2tf32(v.z); v.w = f2tf32(v.w);
    ((float4*)g_xr)[i] = v;
}

// Same decode as the in-kernel Wh preload, but writes per-block global frags.
__global__ void prep_WxF(const float* __restrict__ Wx) {
    int ni = blockIdx.x;            // 0..127
    int j0 = ni * 8;
    int tid = threadIdx.x;          // 256
    for (int idx = tid; idx < 32768; idx += 256) {
        int kb     = idx >> 8;
        int within = idx & 255;
        int q      = within >> 7;
        int rest   = within & 127;
        int lane_i = rest >> 2;
        int sub    = rest & 3;
        int gate   = q * 2 + (sub >> 1);
        int s      = sub & 1;
        int g8     = lane_i >> 2;
        int t4v    = lane_i & 3;
        int k      = kb * 8 + s * 4 + t4v;
        g_WxF[(size_t)ni * 32768 + idx] =
            f2tf32(Wx[(size_t)k * NGATE + gate * HID + j0 + g8]);
    }
}

// ---------------- persistent fused recurrence ----------------
// 128 blocks, 256 threads (8 warps). Block b owns gate-columns [8b, 8b+8) of
// each gate. K-loop per step = 32 chunks of 64: chunks 0-15 = masked h @ Wh
// (Wh frags resident in SMEM), chunks 16-31 = x[t] @ Wx (Wx frags streamed
// via 3-stage cp.async ring, 8KB chunks). Bias added in epilogue.

#define A_STRIDE 68              // 64 + 4 pad, conflict-free frag loads
#define A_BUF    (16 * A_STRIDE) // 1088 floats per buffer
#define BFRAG_FLOATS 32768       // 128 kblocks * 256 (Wh, resident)
#define WXS_FLOATS   (3 * 2048)  // 3-stage Wx ring (8KB chunks)
#define SMEM_FLOATS (BFRAG_FLOATS + 8 * 2 * A_BUF + WXS_FLOATS)

__global__ __launch_bounds__(256, 1) void lstm_persistent(
        const float* __restrict__ mask,
        const float* __restrict__ Wh,
        const float* __restrict__ bias,
        float* __restrict__ out_hs) {
    extern __shared__ float smem[];
    float* Bfrag = smem;                              // 128 KB (Wh)
    float* Ast   = smem + BFRAG_FLOATS;               // per-warp A stages
    float* WxS   = smem + BFRAG_FLOATS + 8 * 2 * A_BUF;  // Wx ring
    const uint32_t wxs_base = (uint32_t)__cvta_generic_to_shared(WxS);

    const int tid  = threadIdx.x;
    const int warp = tid >> 5, lane = tid & 31;
    const int g  = lane >> 2, t4 = lane & 3;
    const int j0 = blockIdx.x * 8;
    const int rb = warp * 16;
    const int hi = lane >> 4;            // staging row parity
    const int colb = j0 + 2 * t4;        // even column base for float2 epilogue
    float* Aw = Ast + warp * 2 * A_BUF;
    const float* wxsrc = g_WxF + (size_t)blockIdx.x * 32768;

    // ---- preload Wh fragments (once per launch) ----
    for (int idx = tid; idx < BFRAG_FLOATS; idx += 256) {
        int kb     = idx >> 8;
        int within = idx & 255;
        int q      = within >> 7;
        int rest   = within & 127;
        int lane_i = rest >> 2;
        int sub    = rest & 3;
        int gate   = q * 2 + (sub >> 1);
        int s      = sub & 1;
        int g8     = lane_i >> 2;
        int t4v    = lane_i & 3;
        int k      = kb * 8 + s * 4 + t4v;
        Bfrag[idx] = f2tf32(Wh[(size_t)k * NGATE + gate * HID + j0 + g8]);
    }
    __syncthreads();

    // bias (resident registers)
    float2 bsv[4];
#pragma unroll
    for (int gate = 0; gate < 4; gate++)
        bsv[gate] = __ldg((const float2*)&bias[gate * HID + colb]);

    // per-step scalars for step 0
    float msk[8], emsk0, emsk1;
    {
        const float* mrow = mask;
#pragma unroll
        for (int i = 0; i < 8; i++) msk[i] = 1.0f - __ldg(&mrow[rb + 2 * i + hi]);
        emsk0 = 1.0f - __ldg(&mrow[rb + g]);
        emsk1 = 1.0f - __ldg(&mrow[rb + g + 8]);
    }

    for (int t = 0; t < T_STEPS; t++) {
        const float* __restrict__ h_in  = g_h[t & 1];
        float*       __restrict__ h_out = g_h[(t + 1) & 1];
        const float* __restrict__ xr_t  = g_xr + (size_t)t * BATCH * DIN;

        // Wx ring prologue: issue chunks 0,1,2 (static data; overlaps phase 1)
#pragma unroll
        for (int xc = 0; xc < 3; xc++) {
#pragma unroll
            for (int i = 0; i < 2; i++) {
                int o = tid + i * 256;                    // float4 index 0..511
                cp_async16(wxs_base + (uint32_t)(xc * 2048 + o * 4) * 4,
                           wxsrc + (size_t)xc * 2048 + o * 4);
            }
            asm volatile("cp.async.commit_group;");
        }

        float nmsk[8] = {0.f, 0.f, 0.f, 0.f, 0.f, 0.f, 0.f, 0.f};
        float nem0 = 0.f, nem1 = 0.f;

        float acc[4][4];
#pragma unroll
        for (int a = 0; a < 4; a++)
#pragma unroll
            for (int c = 0; c < 4; c++) acc[a][c] = 0.f;

        // stage chunk 0 (h, masked)
        float4 ld[8];
#pragma unroll
        for (int i = 0; i < 8; i++) {
            int f = i * 32 + lane;
            int row = f >> 4, quad = f & 15;
            ld[i] = *(const float4*)&h_in[(rb + row) * HID + quad * 4];
        }
#pragma unroll
        for (int i = 0; i < 8; i++) {
            int f = i * 32 + lane;
            int row = f >> 4, quad = f & 15;
            float4 v = ld[i];
            float sc = msk[i];
            v.x = f2tf32(v.x * sc); v.y = f2tf32(v.y * sc);
            v.z = f2tf32(v.z * sc); v.w = f2tf32(v.w * sc);
            *(float4*)&Aw[row * A_STRIDE + quad * 4] = v;
        }
        __syncwarp();

        for (int c = 0; c < 32; c++) {
            const uint32_t* Au = (const uint32_t*)(Aw + (c & 1) * A_BUF);
            // prefetch next A chunk into registers (h for c+1<16, else x)
            if (c < 31) {
                const float* src = (c + 1 < 16) ? (h_in + (c + 1) * 64)
                                                : (xr_t + (c + 1 - 16) * 64);
#pragma unroll
                for (int i = 0; i < 8; i++) {
                    int f = i * 32 + lane;
                    int row = f >> 4, quad = f & 15;
                    ld[i] = *(const float4*)&src[(rb + row) * 1024 + quad * 4];
                }
            }
            if (c == 7 && t + 1 < T_STEPS) {
                const float* nmrow = mask + (size_t)(t + 1) * BATCH;
#pragma unroll
                for (int i = 0; i < 8; i++) nmsk[i] = 1.0f - __ldg(&nmrow[rb + 2 * i + hi]);
                nem0 = 1.0f - __ldg(&nmrow[rb + g]);
                nem1 = 1.0f - __ldg(&nmrow[rb + g + 8]);
            }

            const float* Bb0;
            if (c < 16) {
                Bb0 = Bfrag + c * 8 * 256;
            } else {
                int xc = c - 16;
                asm volatile("cp.async.wait_group 2;");
                __syncthreads();          // all threads' async for xc landed
                Bb0 = WxS + (xc % 3) * 2048;
            }

#pragma unroll
            for (int kb8 = 0; kb8 < 8; kb8++) {
                int kk = kb8 * 8;
                uint32_t afr[4];
                afr[0] = Au[g * A_STRIDE + kk + t4];
                afr[1] = Au[(g + 8) * A_STRIDE + kk + t4];
                afr[2] = Au[g * A_STRIDE + kk + t4 + 4];
                afr[3] = Au[(g + 8) * A_STRIDE + kk + t4 + 4];
                const float* Bb = Bb0 + kb8 * 256;
                float4 bA = *(const float4*)&Bb[lane * 4];        // gates 0,1
                float4 bB = *(const float4*)&Bb[128 + lane * 4];  // gates 2,3
                uint32_t b0[2] = {__float_as_uint(bA.x), __float_as_uint(bA.y)};
                uint32_t b1[2] = {__float_as_uint(bA.z), __float_as_uint(bA.w)};
                uint32_t b2[2] = {__float_as_uint(bB.x), __float_as_uint(bB.y)};
                uint32_t b3[2] = {__float_as_uint(bB.z), __float_as_uint(bB.w)};
                mma_tf32(acc[0], afr, b0);
                mma_tf32(acc[1], afr, b1);
                mma_tf32(acc[2], afr, b2);
                mma_tf32(acc[3], afr, b3);
            }

            if (c >= 16) {
                int xc = c - 16;
                __syncthreads();          // all warps done reading slot xc%3
                if (xc + 3 < 16) {
#pragma unroll
                    for (int i = 0; i < 2; i++) {
                        int o = tid + i * 256;
                        cp_async16(wxs_base + (uint32_t)((xc % 3) * 2048 + o * 4) * 4,
                                   wxsrc + (size_t)(xc + 3) * 2048 + o * 4);
                    }
                }
                asm volatile("cp.async.commit_group;");
            }

            // store prefetched A chunk to the other buffer
            if (c < 31) {
                float* An = Aw + ((c + 1) & 1) * A_BUF;
                bool is_h = (c + 1 < 16);
#pragma unroll
                for (int i = 0; i < 8; i++) {
                    int f = i * 32 + lane;
                    int row = f >> 4, quad = f & 15;
                    float4 v = ld[i];
                    float sc = is_h ? msk[i] : 1.0f;
                    v.x = f2tf32(v.x * sc); v.y = f2tf32(v.y * sc);
                    v.z = f2tf32(v.z * sc); v.w = f2tf32(v.w * sc);
                    *(float4*)&An[row * A_STRIDE + quad * 4] = v;
                }
            }
            __syncwarp();
        }

        // epilogue: bias + LSTM pointwise + state/output writes
#pragma unroll
        for (int r = 0; r < 2; r++) {
            int row = rb + g + r * 8;
            float em = r ? emsk1 : emsk0;
            float2 cp = *(const float2*)&g_c[row * HID + colb];
            float iv0 = acc[0][2 * r]     + bsv[0].x;
            float iv1 = acc[0][2 * r + 1] + bsv[0].y;
            float fv0 = acc[1][2 * r]     + bsv[1].x;
            float fv1 = acc[1][2 * r + 1] + bsv[1].y;
            float ov0 = acc[2][2 * r]     + bsv[2].x;
            float ov1 = acc[2][2 * r + 1] + bsv[2].y;
            float gv0 = acc[3][2 * r]     + bsv[3].x;
            float gv1 = acc[3][2 * r + 1] + bsv[3].y;
            float cn0 = sigmoidf_fast(fv0) * (cp.x * em) + sigmoidf_fast(iv0) * tanhf_fast(gv0);
            float cn1 = sigmoidf_fast(fv1) * (cp.y * em) + sigmoidf_fast(iv1) * tanhf_fast(gv1);
            float hn0 = sigmoidf_fast(ov0) * tanhf_fast(cn0);
            float hn1 = sigmoidf_fast(ov1) * tanhf_fast(cn1);
            *(float2*)&g_c[row * HID + colb]   = make_float2(cn0, cn1);
            *(float2*)&h_out[row * HID + colb] = make_float2(hn0, hn1);
            *(float2*)&out_hs[((size_t)t * BATCH + row) * HID + colb] = make_float2(hn0, hn1);
        }

        grid_sync((unsigned)t);

#pragma unroll
        for (int i = 0; i < 8; i++) msk[i] = nmsk[i];
        emsk0 = nem0; emsk1 = nem1;
    }
}

// ---------------- final state writeback ----------------

__global__ void write_final(float* __restrict__ out) {
    int idx = blockIdx.x * blockDim.x + threadIdx.x;
    if (idx < BATCH * HID) {
        int b = idx / HID, j = idx % HID;
        size_t base = (size_t)T_STEPS * BATCH * HID;
        out[base + (size_t)b * 2 * HID + j]       = g_c[idx];
        out[base + (size_t)b * 2 * HID + HID + j] = g_h[T_STEPS & 1][idx];
    }
}

// ---------------- launch ----------------

extern "C" void kernel_launch(void* const* d_in, const int* in_sizes, int n_in,
                              void* d_out, int out_size) {
    const float* x    = (const float*)d_in[0];  // [T,B,D]
    const float* mask = (const float*)d_in[1];  // [T,B,1]
    const float* csh  = (const float*)d_in[2];  // [B,2H]
    const float* Wx   = (const float*)d_in[3];  // [D,4H]
    const float* Wh   = (const float*)d_in[4];  // [H,4H]
    const float* bias = (const float*)d_in[5];  // [4H]
    float* out = (float*)d_out;

    cudaFuncSetAttribute(lstm_persistent,
                         cudaFuncAttributeMaxDynamicSharedMemorySize,
                         SMEM_FLOATS * (int)sizeof(float));

    init_state<<<(BATCH * HID + 255) / 256, 256>>>(csh);

    prep_xr<<<(T_STEPS * BATCH * DIN / 4 + 255) / 256, 256>>>(x);
    prep_WxF<<<NBLK, 256>>>(Wx);

    lstm_persistent<<<NBLK, 256, SMEM_FLOATS * sizeof(float)>>>(mask, Wh, bias, out);

    write_final<<<(BATCH * HID + 255) / 256, 256>>>(out);
}

// round 12
// speedup vs baseline: 1.6216x; 1.6216x over previous
#include <cuda_runtime.h>
#include <cstdint>

#define T_STEPS 256
#define BATCH   128
#define DIN     1024
#define HID     1024
#define NGATE   4096  // 4*HID
#define NBLK    128

// Scratch (device globals; no allocation allowed in kernel_launch).
__device__ float g_G[(size_t)T_STEPS * BATCH * NGATE];   // x@Wx + b (512 MB)
__device__ float g_xA[(size_t)T_STEPS * BATCH * DIN];    // x, tf32-rounded, A-fragment order (128 MB)
__device__ float g_WxB[(size_t)DIN * NGATE];             // Wx, tf32-rounded, B-fragment order (16 MB)
__device__ float g_h0[BATCH * HID];                      // initial hidden state
__device__ float g_c[BATCH * HID];                       // cell state
__device__ unsigned g_cnt;                               // barrier arrive counter
__device__ volatile unsigned g_gen;                      // barrier generation

// ---------------- helpers ----------------

__device__ __forceinline__ float f2tf32(float x) {
    uint32_t u;
    asm("cvt.rna.tf32.f32 %0, %1;" : "=r"(u) : "f"(x));
    return __uint_as_float(u);
}

__device__ __forceinline__ void mma_tf32(float c[4], const uint32_t a[4], const uint32_t b[2]) {
    asm volatile(
        "mma.sync.aligned.m16n8k8.row.col.f32.tf32.tf32.f32 "
        "{%0,%1,%2,%3}, {%4,%5,%6,%7}, {%8,%9}, {%0,%1,%2,%3};"
        : "+f"(c[0]), "+f"(c[1]), "+f"(c[2]), "+f"(c[3])
        : "r"(a[0]), "r"(a[1]), "r"(a[2]), "r"(a[3]), "r"(b[0]), "r"(b[1]));
}

__device__ __forceinline__ void cp_async16(uint32_t dst_smem, const void* src) {
    asm volatile("cp.async.ca.shared.global [%0], [%1], 16;" :: "r"(dst_smem), "l"(src));
}

__device__ __forceinline__ float sigmoidf_fast(float x) {
    x = fminf(fmaxf(x, -30.f), 30.f);
    return __fdividef(1.f, 1.f + __expf(-x));
}

__device__ __forceinline__ float tanhf_fast(float x) {
    x = fminf(fmaxf(x, -15.f), 15.f);
    float e = __expf(2.f * x);
    return __fdividef(e - 1.f, e + 1.f);
}

// Software grid barrier (R9-proven atomic-counter version).
__device__ __forceinline__ void grid_sync(unsigned step) {
    __syncthreads();
    if (threadIdx.x == 0) {
        __threadfence();
        unsigned a = atomicAdd(&g_cnt, 1u);
        if (a == gridDim.x - 1) {
            g_cnt = 0;
            __threadfence();
            g_gen = step + 1;
        } else {
            while (g_gen < step + 1) __nanosleep(32);
        }
        __threadfence();
    }
    __syncthreads();
}

// ---------------- init state + barrier ----------------

__global__ void init_state(const float* __restrict__ csh) {
    int idx = blockIdx.x * blockDim.x + threadIdx.x;
    if (idx == 0) { g_cnt = 0; g_gen = 0; }
    if (idx < BATCH * HID) {
        int b = idx / HID, j = idx % HID;
        g_c[idx]  = csh[b * 2 * HID + j];          // cell first
        g_h0[idx] = csh[b * 2 * HID + HID + j];    // hidden second
    }
}

// ---------------- prep: permute+round x and Wx into fragment tile order ----

__global__ void prep_xA(const float* __restrict__ x) {
    __shared__ float tl[128 * 33];
    int ki = blockIdx.x, mi = blockIdx.y;
    int tid = threadIdx.x;  // 256
    for (int i = 0; i < 16; i++) {
        int e = tid + i * 256, r = e >> 5, c = e & 31;
        tl[r * 33 + c] = x[(size_t)(mi * 128 + r) * DIN + ki * 32 + c];
    }
    __syncthreads();
    size_t base = ((size_t)mi * 32 + ki) << 12;  // *4096
    for (int i = 0; i < 4; i++) {
        int o = tid + i * 256;           // float4 index 0..1023
        int lane = o & 31, mt = (o >> 5) & 1, wm = (o >> 6) & 3, k8 = o >> 8;
        int g = lane >> 2, t4 = lane & 3;
        int r0 = wm * 32 + mt * 16 + g, r1 = r0 + 8;
        int ka = k8 * 8 + t4, kb = ka + 4;
        float4 v;
        v.x = f2tf32(tl[r0 * 33 + ka]);
        v.y = f2tf32(tl[r1 * 33 + ka]);
        v.z = f2tf32(tl[r0 * 33 + kb]);
        v.w = f2tf32(tl[r1 * 33 + kb]);
        ((float4*)(g_xA + base))[o] = v;
    }
}

__global__ void prep_WxB(const float* __restrict__ Wx) {
    __shared__ float tl[32 * 129];
    int ni = blockIdx.x, ki = blockIdx.y;
    int tid = threadIdx.x;  // 256
    for (int i = 0; i < 16; i++) {
        int e = tid + i * 256, r = e >> 7, c = e & 127;
        tl[r * 129 + c] = Wx[(size_t)(ki * 32 + r) * NGATE + ni * 128 + c];
    }
    __syncthreads();
    size_t base = ((size_t)ki * 32 + ni) << 12;
    for (int i = 0; i < 4; i++) {
        int o = tid + i * 256;
        int lane = o & 31, w = (o >> 5) & 3, wn = (o >> 7) & 1, k8 = o >> 8;
        int g = lane >> 2, t4 = lane & 3;
        int c0 = wn * 64 + (2 * w) * 8 + g, c1 = c0 + 8;
        int ka = k8 * 8 + t4, kb = ka + 4;
        float4 v;
        v.x = f2tf32(tl[ka * 129 + c0]);
        v.y = f2tf32(tl[kb * 129 + c0]);
        v.z = f2tf32(tl[ka * 129 + c1]);
        v.w = f2tf32(tl[kb * 129 + c1]);
        ((float4*)(g_WxB + base))[o] = v;
    }
}

// ---------------- pre-GEMM: G = x @ Wx + bias ----------------
// Tile 128x128x32; fragment-ordered tiles; 6 LDS.128 per 16 mma; 3-stage cp.async.

#define PG_STAGE_FLOATS 8192       // A 4096 + B 4096 = 32 KB
#define PG_STAGES 3
#define PG_SMEM_BYTES (PG_STAGES * PG_STAGE_FLOATS * 4)  // 96 KB

__device__ __forceinline__ void pg_fill(uint32_t sstage, int mi, int ni, int kt, int tid) {
#pragma unroll
    for (int i = 0; i < 4; i++) {
        int o = tid + i * 256;
        cp_async16(sstage + (uint32_t)o * 16, g_xA + (((size_t)mi * 32 + kt) << 12) + o * 4);
    }
#pragma unroll
    for (int i = 0; i < 4; i++) {
        int o = tid + i * 256;
        cp_async16(sstage + 16384 + (uint32_t)o * 16, g_WxB + (((size_t)kt * 32 + ni) << 12) + o * 4);
    }
}

__global__ __launch_bounds__(256, 2) void pregemm(const float* __restrict__ bias) {
    extern __shared__ float sm[];
    const uint32_t sbase = (uint32_t)__cvta_generic_to_shared(sm);

    const int tid  = threadIdx.x;
    const int warp = tid >> 5, lane = tid & 31;
    const int g  = lane >> 2, t4 = lane & 3;
    const int wm = warp >> 1, wn = warp & 1;
    const int ni = blockIdx.x, mi = blockIdx.y;
    const int m0 = mi * 128, n0 = ni * 128;

    float acc[2][8][4];
#pragma unroll
    for (int a = 0; a < 2; a++)
#pragma unroll
        for (int b = 0; b < 8; b++)
#pragma unroll
            for (int c = 0; c < 4; c++) acc[a][b][c] = 0.f;

    pg_fill(sbase, mi, ni, 0, tid);
    asm volatile("cp.async.commit_group;");
    pg_fill(sbase + PG_STAGE_FLOATS * 4, mi, ni, 1, tid);
    asm volatile("cp.async.commit_group;");

    for (int kt = 0; kt < 32; kt++) {
        asm volatile("cp.async.wait_group 1;");
        __syncthreads();

        if (kt + 2 < 32)
            pg_fill(sbase + (uint32_t)((kt + 2) % PG_STAGES) * PG_STAGE_FLOATS * 4,
                    mi, ni, kt + 2, tid);
        asm volatile("cp.async.commit_group;");

        const float* st  = sm + (kt % PG_STAGES) * PG_STAGE_FLOATS;
        const float* stA = st;
        const float* stB = st + 4096;
#pragma unroll
        for (int k8 = 0; k8 < 4; k8++) {
            float4 fa0 = *(const float4*)&stA[k8 * 1024 + wm * 256 + lane * 4];
            float4 fa1 = *(const float4*)&stA[k8 * 1024 + wm * 256 + 128 + lane * 4];
            uint32_t a0[4] = {__float_as_uint(fa0.x), __float_as_uint(fa0.y),
                              __float_as_uint(fa0.z), __float_as_uint(fa0.w)};
            uint32_t a1[4] = {__float_as_uint(fa1.x), __float_as_uint(fa1.y),
                              __float_as_uint(fa1.z), __float_as_uint(fa1.w)};
#pragma unroll
            for (int w = 0; w < 4; w++) {
                float4 fb = *(const float4*)&stB[k8 * 1024 + wn * 512 + w * 128 + lane * 4];
                uint32_t b0[2] = {__float_as_uint(fb.x), __float_as_uint(fb.y)};
                uint32_t b1[2] = {__float_as_uint(fb.z), __float_as_uint(fb.w)};
                mma_tf32(acc[0][2 * w],     a0, b0);
                mma_tf32(acc[1][2 * w],     a1, b0);
                mma_tf32(acc[0][2 * w + 1], a0, b1);
                mma_tf32(acc[1][2 * w + 1], a1, b1);
            }
        }
    }

#pragma unroll
    for (int mt = 0; mt < 2; mt++) {
#pragma unroll
        for (int nt = 0; nt < 8; nt++) {
            int r = m0 + wm * 32 + mt * 16 + g;
            int c = n0 + wn * 64 + nt * 8 + 2 * t4;
            float b0 = bias[c], b1 = bias[c + 1];
            float2 v0 = make_float2(acc[mt][nt][0] + b0, acc[mt][nt][1] + b1);
            float2 v1 = make_float2(acc[mt][nt][2] + b0, acc[mt][nt][3] + b1);
            *(float2*)&g_G[(size_t)r * NGATE + c]       = v0;
            *(float2*)&g_G[(size_t)(r + 8) * NGATE + c] = v1;
        }
    }
}

// ---------------- persistent recurrence ----------------
// R9 structure; single change: h history lives in out_hs (step t reads
// out_hs[t-1], t=0 reads g_h0). No separate h double-buffer stores.

#define A_STRIDE 68              // 64 + 4 pad, conflict-free frag loads
#define A_BUF    (16 * A_STRIDE) // 1088 floats per buffer
#define BFRAG_FLOATS 32768       // 128 kblocks * 256
#define SMEM_FLOATS (BFRAG_FLOATS + 8 * 2 * A_BUF)

__global__ __launch_bounds__(256, 1) void lstm_persistent(
        const float* __restrict__ mask,
        const float* __restrict__ Wh,
        float* __restrict__ out_hs) {
    extern __shared__ float smem[];
    float* Bfrag = smem;                 // 128 KB
    float* Ast   = smem + BFRAG_FLOATS;  // 8 warps * 2 bufs * 1088 floats

    const int tid  = threadIdx.x;
    const int warp = tid >> 5, lane = tid & 31;
    const int g  = lane >> 2, t4 = lane & 3;
    const int j0 = blockIdx.x * 8;
    const int rb = warp * 16;
    const int hi = lane >> 4;            // staging row parity
    const int colb = j0 + 2 * t4;        // even column base for float2 epilogue
    float* Aw = Ast + warp * 2 * A_BUF;

    for (int idx = tid; idx < BFRAG_FLOATS; idx += 256) {
        int kb     = idx >> 8;
        int within = idx & 255;
        int q      = within >> 7;
        int rest   = within & 127;
        int lane_i = rest >> 2;
        int sub    = rest & 3;
        int gate   = q * 2 + (sub >> 1);
        int s      = sub & 1;
        int g8     = lane_i >> 2;
        int t4v    = lane_i & 3;
        int k      = kb * 8 + s * 4 + t4v;
        Bfrag[idx] = f2tf32(Wh[(size_t)k * NGATE + gate * HID + j0 + g8]);
    }
    __syncthreads();

    float msk[8], emsk0, emsk1;
    float2 pG[4][2];
    {
        const float* mrow = mask;
#pragma unroll
        for (int i = 0; i < 8; i++) msk[i] = 1.0f - __ldg(&mrow[rb + 2 * i + hi]);
        emsk0 = 1.0f - __ldg(&mrow[rb + g]);
        emsk1 = 1.0f - __ldg(&mrow[rb + g + 8]);
#pragma unroll
        for (int r = 0; r < 2; r++) {
            size_t gb = ((size_t)(rb + g + r * 8)) * NGATE + colb;
#pragma unroll
            for (int gate = 0; gate < 4; gate++)
                pG[gate][r] = __ldg((const float2*)&g_G[gb + gate * HID]);
        }
    }

    for (int t = 0; t < T_STEPS; t++) {
        const float* __restrict__ h_in =
            (t == 0) ? g_h0 : (out_hs + (size_t)(t - 1) * BATCH * HID);

        float nmsk[8] = {0.f, 0.f, 0.f, 0.f, 0.f, 0.f, 0.f, 0.f};
        float nem0 = 0.f, nem1 = 0.f;
        float2 nG[4][2];
#pragma unroll
        for (int gate = 0; gate < 4; gate++) {
            nG[gate][0] = make_float2(0.f, 0.f);
            nG[gate][1] = make_float2(0.f, 0.f);
        }

        float acc[4][4];
#pragma unroll
        for (int a = 0; a < 4; a++)
#pragma unroll
            for (int c = 0; c < 4; c++) acc[a][c] = 0.f;

        float4 ld[8];
#pragma unroll
        for (int i = 0; i < 8; i++) {
            int f = i * 32 + lane;
            int row = f >> 4, quad = f & 15;
            ld[i] = *(const float4*)&h_in[(rb + row) * HID + quad * 4];
        }
#pragma unroll
        for (int i = 0; i < 8; i++) {
            int f = i * 32 + lane;
            int row = f >> 4, quad = f & 15;
            float4 v = ld[i];
            float sc = msk[i];
            v.x = f2tf32(v.x * sc); v.y = f2tf32(v.y * sc);
            v.z = f2tf32(v.z * sc); v.w = f2tf32(v.w * sc);
            *(float4*)&Aw[row * A_STRIDE + quad * 4] = v;
        }
        __syncwarp();

        for (int c = 0; c < 16; c++) {
            const uint32_t* Au = (const uint32_t*)(Aw + (c & 1) * A_BUF);
            if (c < 15) {
#pragma unroll
                for (int i = 0; i < 8; i++) {
                    int f = i * 32 + lane;
                    int row = f >> 4, quad = f & 15;
                    ld[i] = *(const float4*)&h_in[(rb + row) * HID + (c + 1) * 64 + quad * 4];
                }
            }
            if (c == 7 && t + 1 < T_STEPS) {
                const float* nmrow = mask + (size_t)(t + 1) * BATCH;
#pragma unroll
                for (int i = 0; i < 8; i++) nmsk[i] = 1.0f - __ldg(&nmrow[rb + 2 * i + hi]);
                nem0 = 1.0f - __ldg(&nmrow[rb + g]);
                nem1 = 1.0f - __ldg(&nmrow[rb + g + 8]);
#pragma unroll
                for (int r = 0; r < 2; r++) {
                    size_t gb = ((size_t)(t + 1) * BATCH + rb + g + r * 8) * NGATE + colb;
#pragma unroll
                    for (int gate = 0; gate < 4; gate++)
                        nG[gate][r] = __ldg((const float2*)&g_G[gb + gate * HID]);
                }
            }
#pragma unroll
            for (int kb8 = 0; kb8 < 8; kb8++) {
                int kk = kb8 * 8;
                uint32_t afr[4];
                afr[0] = Au[g * A_STRIDE + kk + t4];
                afr[1] = Au[(g + 8) * A_STRIDE + kk + t4];
                afr[2] = Au[g * A_STRIDE + kk + t4 + 4];
                afr[3] = Au[(g + 8) * A_STRIDE + kk + t4 + 4];
                const float* Bb = Bfrag + (c * 8 + kb8) * 256;
                float4 bA = *(const float4*)&Bb[lane * 4];        // gates 0,1
                float4 bB = *(const float4*)&Bb[128 + lane * 4];  // gates 2,3
                uint32_t b0[2] = {__float_as_uint(bA.x), __float_as_uint(bA.y)};
                uint32_t b1[2] = {__float_as_uint(bA.z), __float_as_uint(bA.w)};
                uint32_t b2[2] = {__float_as_uint(bB.x), __float_as_uint(bB.y)};
                uint32_t b3[2] = {__float_as_uint(bB.z), __float_as_uint(bB.w)};
                mma_tf32(acc[0], afr, b0);
                mma_tf32(acc[1], afr, b1);
                mma_tf32(acc[2], afr, b2);
                mma_tf32(acc[3], afr, b3);
            }
            if (c < 15) {
                float* An = Aw + ((c + 1) & 1) * A_BUF;
#pragma unroll
                for (int i = 0; i < 8; i++) {
                    int f = i * 32 + lane;
                    int row = f >> 4, quad = f & 15;
                    float4 v = ld[i];
                    float sc = msk[i];
                    v.x = f2tf32(v.x * sc); v.y = f2tf32(v.y * sc);
                    v.z = f2tf32(v.z * sc); v.w = f2tf32(v.w * sc);
                    *(float4*)&An[row * A_STRIDE + quad * 4] = v;
                }
            }
            __syncwarp();
        }

#pragma unroll
        for (int r = 0; r < 2; r++) {
            int row = rb + g + r * 8;
            float em = r ? emsk1 : emsk0;
            float2 cp = *(const float2*)&g_c[row * HID + colb];
            float iv0 = acc[0][2 * r]     + pG[0][r].x;
            float iv1 = acc[0][2 * r + 1] + pG[0][r].y;
            float fv0 = acc[1][2 * r]     + pG[1][r].x;
            float fv1 = acc[1][2 * r + 1] + pG[1][r].y;
            float ov0 = acc[2][2 * r]     + pG[2][r].x;
            float ov1 = acc[2][2 * r + 1] + pG[2][r].y;
            float gv0 = acc[3][2 * r]     + pG[3][r].x;
            float gv1 = acc[3][2 * r + 1] + pG[3][r].y;
            float cn0 = sigmoidf_fast(fv0) * (cp.x * em) + sigmoidf_fast(iv0) * tanhf_fast(gv0);
            float cn1 = sigmoidf_fast(fv1) * (cp.y * em) + sigmoidf_fast(iv1) * tanhf_fast(gv1);
            float hn0 = sigmoidf_fast(ov0) * tanhf_fast(cn0);
            float hn1 = sigmoidf_fast(ov1) * tanhf_fast(cn1);
            *(float2*)&g_c[row * HID + colb] = make_float2(cn0, cn1);
            *(float2*)&out_hs[((size_t)t * BATCH + row) * HID + colb] = make_float2(hn0, hn1);
        }

        grid_sync((unsigned)t);

#pragma unroll
        for (int i = 0; i < 8; i++) msk[i] = nmsk[i];
        emsk0 = nem0; emsk1 = nem1;
#pragma unroll
        for (int gate = 0; gate < 4; gate++) {
            pG[gate][0] = nG[gate][0];
            pG[gate][1] = nG[gate][1];
        }
    }
}

// ---------------- final state writeback ----------------
// c from g_c; final hidden = hs[T-1] (already in out).

__global__ void write_final(float* __restrict__ out) {
    int idx = blockIdx.x * blockDim.x + threadIdx.x;
    if (idx < BATCH * HID) {
        int b = idx / HID, j = idx % HID;
        size_t base = (size_t)T_STEPS * BATCH * HID;
        out[base + (size_t)b * 2 * HID + j] = g_c[idx];
        out[base + (size_t)b * 2 * HID + HID + j] =
            out[(size_t)(T_STEPS - 1) * BATCH * HID + (size_t)b * HID + j];
    }
}

// ---------------- launch ----------------

extern "C" void kernel_launch(void* const* d_in, const int* in_sizes, int n_in,
                              void* d_out, int out_size) {
    const float* x    = (const float*)d_in[0];  // [T,B,D]
    const float* mask = (const float*)d_in[1];  // [T,B,1]
    const float* csh  = (const float*)d_in[2];  // [B,2H]
    const float* Wx   = (const float*)d_in[3];  // [D,4H]
    const float* Wh   = (const float*)d_in[4];  // [H,4H]
    const float* bias = (const float*)d_in[5];  // [4H]
    float* out = (float*)d_out;

    cudaFuncSetAttribute(lstm_persistent,
                         cudaFuncAttributeMaxDynamicSharedMemorySize,
                         SMEM_FLOATS * (int)sizeof(float));
    cudaFuncSetAttribute(pregemm,
                         cudaFuncAttributeMaxDynamicSharedMemorySize, PG_SMEM_BYTES);

    init_state<<<(BATCH * HID + 255) / 256, 256>>>(csh);

    prep_xA<<<dim3(DIN / 32, (T_STEPS * BATCH) / 128), 256>>>(x);
    prep_WxB<<<dim3(NGATE / 128, DIN / 32), 256>>>(Wx);

    pregemm<<<dim3(NGATE / 128, (T_STEPS * BATCH) / 128), 256, PG_SMEM_BYTES>>>(bias);

    lstm_persistent<<<NBLK, 256, SMEM_FLOATS * sizeof(float)>>>(mask, Wh, out);

    write_final<<<(BATCH * HID + 255) / 256, 256>>>(out);
}

// round 13
// speedup vs baseline: 2.0150x; 1.2426x over previous
#include <cuda_runtime.h>
#include <cstdint>

#define T_STEPS 256
#define BATCH   128
#define DIN     1024
#define HID     1024
#define NGATE   4096  // 4*HID
#define NBLK    128

// Scratch (device globals; no allocation allowed in kernel_launch).
__device__ float g_G[(size_t)T_STEPS * BATCH * NGATE];   // x@Wx + b (512 MB)
__device__ float g_xA[(size_t)T_STEPS * BATCH * DIN];    // x, tf32-rounded, A-fragment order (128 MB)
__device__ float g_WxB[(size_t)DIN * NGATE];             // Wx, tf32-rounded, B-fragment order (16 MB)
__device__ float g_hF[2][BATCH * HID];                   // h (raw fp32), A-FRAGMENT order, dbl-buffered
__device__ float g_c[BATCH * HID];                       // cell state
__device__ unsigned g_cnt;                               // barrier arrive counter
__device__ volatile unsigned g_gen;                      // barrier generation

// ---------------- helpers ----------------

__device__ __forceinline__ float f2tf32(float x) {
    uint32_t u;
    asm("cvt.rna.tf32.f32 %0, %1;" : "=r"(u) : "f"(x));
    return __uint_as_float(u);
}

__device__ __forceinline__ void mma_tf32(float c[4], const uint32_t a[4], const uint32_t b[2]) {
    asm volatile(
        "mma.sync.aligned.m16n8k8.row.col.f32.tf32.tf32.f32 "
        "{%0,%1,%2,%3}, {%4,%5,%6,%7}, {%8,%9}, {%0,%1,%2,%3};"
        : "+f"(c[0]), "+f"(c[1]), "+f"(c[2]), "+f"(c[3])
        : "r"(a[0]), "r"(a[1]), "r"(a[2]), "r"(a[3]), "r"(b[0]), "r"(b[1]));
}

__device__ __forceinline__ void cp_async16(uint32_t dst_smem, const void* src) {
    asm volatile("cp.async.ca.shared.global [%0], [%1], 16;" :: "r"(dst_smem), "l"(src));
}

__device__ __forceinline__ float sigmoidf_fast(float x) {
    x = fminf(fmaxf(x, -30.f), 30.f);
    return __fdividef(1.f, 1.f + __expf(-x));
}

__device__ __forceinline__ float tanhf_fast(float x) {
    x = fminf(fmaxf(x, -15.f), 15.f);
    float e = __expf(2.f * x);
    return __fdividef(e - 1.f, e + 1.f);
}

// Software grid barrier (R9-proven atomic-counter version).
__device__ __forceinline__ void grid_sync(unsigned step) {
    __syncthreads();
    if (threadIdx.x == 0) {
        __threadfence();
        unsigned a = atomicAdd(&g_cnt, 1u);
        if (a == gridDim.x - 1) {
            g_cnt = 0;
            __threadfence();
            g_gen = step + 1;
        } else {
            while (g_gen < step + 1) __nanosleep(32);
        }
        __threadfence();
    }
    __syncthreads();
}

// ---------------- init state + barrier ----------------
// Fragment index for h[row][k]:
//   warp=row/16, g=row%8, r=(row%16)/8, kb8=k/8, t4=k%4, s=(k%8)/4
//   float idx = ((warp*128 + kb8)*32 + g*4 + t4)*4 + (r + 2*s)

__global__ void init_state(const float* __restrict__ csh) {
    int idx = blockIdx.x * blockDim.x + threadIdx.x;
    if (idx == 0) { g_cnt = 0; g_gen = 0; }
    if (idx < BATCH * HID) {
        int row = idx / HID, k = idx % HID;
        g_c[idx] = csh[row * 2 * HID + k];                 // cell first
        float h0 = csh[row * 2 * HID + HID + k];           // hidden second
        int warp = row >> 4, g = row & 7, r = (row >> 3) & 1;
        int kb8 = k >> 3, t4 = k & 3, s = (k >> 2) & 1;
        g_hF[0][((warp * 128 + kb8) * 32 + g * 4 + t4) * 4 + r + 2 * s] = h0;
    }
}

// ---------------- prep: permute+round x and Wx into fragment tile order ----

__global__ void prep_xA(const float* __restrict__ x) {
    __shared__ float tl[128 * 33];
    int ki = blockIdx.x, mi = blockIdx.y;
    int tid = threadIdx.x;  // 256
    for (int i = 0; i < 16; i++) {
        int e = tid + i * 256, r = e >> 5, c = e & 31;
        tl[r * 33 + c] = x[(size_t)(mi * 128 + r) * DIN + ki * 32 + c];
    }
    __syncthreads();
    size_t base = ((size_t)mi * 32 + ki) << 12;  // *4096
    for (int i = 0; i < 4; i++) {
        int o = tid + i * 256;           // float4 index 0..1023
        int lane = o & 31, mt = (o >> 5) & 1, wm = (o >> 6) & 3, k8 = o >> 8;
        int g = lane >> 2, t4 = lane & 3;
        int r0 = wm * 32 + mt * 16 + g, r1 = r0 + 8;
        int ka = k8 * 8 + t4, kb = ka + 4;
        float4 v;
        v.x = f2tf32(tl[r0 * 33 + ka]);
        v.y = f2tf32(tl[r1 * 33 + ka]);
        v.z = f2tf32(tl[r0 * 33 + kb]);
        v.w = f2tf32(tl[r1 * 33 + kb]);
        ((float4*)(g_xA + base))[o] = v;
    }
}

__global__ void prep_WxB(const float* __restrict__ Wx) {
    __shared__ float tl[32 * 129];
    int ni = blockIdx.x, ki = blockIdx.y;
    int tid = threadIdx.x;  // 256
    for (int i = 0; i < 16; i++) {
        int e = tid + i * 256, r = e >> 7, c = e & 127;
        tl[r * 129 + c] = Wx[(size_t)(ki * 32 + r) * NGATE + ni * 128 + c];
    }
    __syncthreads();
    size_t base = ((size_t)ki * 32 + ni) << 12;
    for (int i = 0; i < 4; i++) {
        int o = tid + i * 256;
        int lane = o & 31, w = (o >> 5) & 3, wn = (o >> 7) & 1, k8 = o >> 8;
        int g = lane >> 2, t4 = lane & 3;
        int c0 = wn * 64 + (2 * w) * 8 + g, c1 = c0 + 8;
        int ka = k8 * 8 + t4, kb = ka + 4;
        float4 v;
        v.x = f2tf32(tl[ka * 129 + c0]);
        v.y = f2tf32(tl[kb * 129 + c0]);
        v.z = f2tf32(tl[ka * 129 + c1]);
        v.w = f2tf32(tl[kb * 129 + c1]);
        ((float4*)(g_WxB + base))[o] = v;
    }
}

// ---------------- pre-GEMM: G = x @ Wx + bias ----------------
// Tile 128x128x32; fragment-ordered tiles; 6 LDS.128 per 16 mma; 3-stage cp.async.

#define PG_STAGE_FLOATS 8192       // A 4096 + B 4096 = 32 KB
#define PG_STAGES 3
#define PG_SMEM_BYTES (PG_STAGES * PG_STAGE_FLOATS * 4)  // 96 KB

__device__ __forceinline__ void pg_fill(uint32_t sstage, int mi, int ni, int kt, int tid) {
#pragma unroll
    for (int i = 0; i < 4; i++) {
        int o = tid + i * 256;
        cp_async16(sstage + (uint32_t)o * 16, g_xA + (((size_t)mi * 32 + kt) << 12) + o * 4);
    }
#pragma unroll
    for (int i = 0; i < 4; i++) {
        int o = tid + i * 256;
        cp_async16(sstage + 16384 + (uint32_t)o * 16, g_WxB + (((size_t)kt * 32 + ni) << 12) + o * 4);
    }
}

__global__ __launch_bounds__(256, 2) void pregemm(const float* __restrict__ bias) {
    extern __shared__ float sm[];
    const uint32_t sbase = (uint32_t)__cvta_generic_to_shared(sm);

    const int tid  = threadIdx.x;
    const int warp = tid >> 5, lane = tid & 31;
    const int g  = lane >> 2, t4 = lane & 3;
    const int wm = warp >> 1, wn = warp & 1;
    const int ni = blockIdx.x, mi = blockIdx.y;
    const int m0 = mi * 128, n0 = ni * 128;

    float acc[2][8][4];
#pragma unroll
    for (int a = 0; a < 2; a++)
#pragma unroll
        for (int b = 0; b < 8; b++)
#pragma unroll
            for (int c = 0; c < 4; c++) acc[a][b][c] = 0.f;

    pg_fill(sbase, mi, ni, 0, tid);
    asm volatile("cp.async.commit_group;");
    pg_fill(sbase + PG_STAGE_FLOATS * 4, mi, ni, 1, tid);
    asm volatile("cp.async.commit_group;");

    for (int kt = 0; kt < 32; kt++) {
        asm volatile("cp.async.wait_group 1;");
        __syncthreads();

        if (kt + 2 < 32)
            pg_fill(sbase + (uint32_t)((kt + 2) % PG_STAGES) * PG_STAGE_FLOATS * 4,
                    mi, ni, kt + 2, tid);
        asm volatile("cp.async.commit_group;");

        const float* st  = sm + (kt % PG_STAGES) * PG_STAGE_FLOATS;
        const float* stA = st;
        const float* stB = st + 4096;
#pragma unroll
        for (int k8 = 0; k8 < 4; k8++) {
            float4 fa0 = *(const float4*)&stA[k8 * 1024 + wm * 256 + lane * 4];
            float4 fa1 = *(const float4*)&stA[k8 * 1024 + wm * 256 + 128 + lane * 4];
            uint32_t a0[4] = {__float_as_uint(fa0.x), __float_as_uint(fa0.y),
                              __float_as_uint(fa0.z), __float_as_uint(fa0.w)};
            uint32_t a1[4] = {__float_as_uint(fa1.x), __float_as_uint(fa1.y),
                              __float_as_uint(fa1.z), __float_as_uint(fa1.w)};
#pragma unroll
            for (int w = 0; w < 4; w++) {
                float4 fb = *(const float4*)&stB[k8 * 1024 + wn * 512 + w * 128 + lane * 4];
                uint32_t b0[2] = {__float_as_uint(fb.x), __float_as_uint(fb.y)};
                uint32_t b1[2] = {__float_as_uint(fb.z), __float_as_uint(fb.w)};
                mma_tf32(acc[0][2 * w],     a0, b0);
                mma_tf32(acc[1][2 * w],     a1, b0);
                mma_tf32(acc[0][2 * w + 1], a0, b1);
                mma_tf32(acc[1][2 * w + 1], a1, b1);
            }
        }
    }

#pragma unroll
    for (int mt = 0; mt < 2; mt++) {
#pragma unroll
        for (int nt = 0; nt < 8; nt++) {
            int r = m0 + wm * 32 + mt * 16 + g;
            int c = n0 + wn * 64 + nt * 8 + 2 * t4;
            float b0 = bias[c], b1 = bias[c + 1];
            float2 v0 = make_float2(acc[mt][nt][0] + b0, acc[mt][nt][1] + b1);
            float2 v1 = make_float2(acc[mt][nt][2] + b0, acc[mt][nt][3] + b1);
            *(float2*)&g_G[(size_t)r * NGATE + c]       = v0;
            *(float2*)&g_G[(size_t)(r + 8) * NGATE + c] = v1;
        }
    }
}

// ---------------- persistent recurrence ----------------
// 128 blocks, 256 threads (8 warps). Block b owns gate-columns [8b,8b+8).
// A fragments read DIRECTLY from g_hF (fragment-ordered, 1 coalesced LDG.128
// per lane per kb8, ring-16 prefetch) — no smem staging at all. Mask applied
// at frag load. Epilogue writes raw h into next buffer's kb8=blockIdx slice.

#define BFRAG_FLOATS 32768       // 128 kblocks * 256 (Wh, resident)
#define LS_SMEM_BYTES (BFRAG_FLOATS * 4)  // 128 KB
#define RING 16

__global__ __launch_bounds__(256, 1) void lstm_persistent(
        const float* __restrict__ mask,
        const float* __restrict__ Wh,
        float* __restrict__ out_hs) {
    extern __shared__ float smem[];
    float* Bfrag = smem;

    const int tid  = threadIdx.x;
    const int warp = tid >> 5, lane = tid & 31;
    const int g  = lane >> 2, t4 = lane & 3;
    const int bx = blockIdx.x;
    const int j0 = bx * 8;
    const int rb = warp * 16;
    const int colb = j0 + 2 * t4;

    // epilogue fragment-store offsets (within this warp's kb8=bx tile)
    const int krel0 = 2 * t4, krel1 = 2 * t4 + 1;
    const int off0 = (g * 4 + (krel0 & 3)) * 4 + 2 * ((krel0 >> 2) & 1);
    const int off1 = (g * 4 + (krel1 & 3)) * 4 + 2 * ((krel1 >> 2) & 1);

    // ---- preload Wh fragments (once per launch) ----
    for (int idx = tid; idx < BFRAG_FLOATS; idx += 256) {
        int kb     = idx >> 8;
        int within = idx & 255;
        int q      = within >> 7;
        int rest   = within & 127;
        int lane_i = rest >> 2;
        int sub    = rest & 3;
        int gate   = q * 2 + (sub >> 1);
        int s      = sub & 1;
        int g8     = lane_i >> 2;
        int t4v    = lane_i & 3;
        int k      = kb * 8 + s * 4 + t4v;
        Bfrag[idx] = f2tf32(Wh[(size_t)k * NGATE + gate * HID + j0 + g8]);
    }
    __syncthreads();

    // per-step scalars for step 0
    float em0, em1;
    float2 pG[4][2];
    {
        em0 = 1.0f - __ldg(&mask[rb + g]);
        em1 = 1.0f - __ldg(&mask[rb + g + 8]);
#pragma unroll
        for (int r = 0; r < 2; r++) {
            size_t gb = ((size_t)(rb + g + r * 8)) * NGATE + colb;
#pragma unroll
            for (int gate = 0; gate < 4; gate++)
                pG[gate][r] = __ldg((const float2*)&g_G[gb + gate * HID]);
        }
    }

    for (int t = 0; t < T_STEPS; t++) {
        const float* __restrict__ hF_in = g_hF[t & 1] + (size_t)warp * 16384;  // 128 kb8 * 128 floats
        float*       __restrict__ hF_out = g_hF[(t + 1) & 1];

        float nem0 = 0.f, nem1 = 0.f;
        float2 nG[4][2];
#pragma unroll
        for (int gate = 0; gate < 4; gate++) {
            nG[gate][0] = make_float2(0.f, 0.f);
            nG[gate][1] = make_float2(0.f, 0.f);
        }

        float acc[4][4];
#pragma unroll
        for (int a = 0; a < 4; a++)
#pragma unroll
            for (int c = 0; c < 4; c++) acc[a][c] = 0.f;

        // ring prologue: 16 outstanding coalesced LDG.128
        float4 ring[RING];
#pragma unroll
        for (int p = 0; p < RING; p++)
            ring[p] = *(const float4*)&hF_in[p * 128 + lane * 4];

#pragma unroll 16
        for (int kb8 = 0; kb8 < 128; kb8++) {
            float4 av = ring[kb8 & (RING - 1)];
            if (kb8 < 128 - RING)
                ring[kb8 & (RING - 1)] =
                    *(const float4*)&hF_in[(kb8 + RING) * 128 + lane * 4];

            if (kb8 == 64 && t + 1 < T_STEPS) {
                const float* nmrow = mask + (size_t)(t + 1) * BATCH;
                nem0 = 1.0f - __ldg(&nmrow[rb + g]);
                nem1 = 1.0f - __ldg(&nmrow[rb + g + 8]);
#pragma unroll
                for (int r = 0; r < 2; r++) {
                    size_t gb = ((size_t)(t + 1) * BATCH + rb + g + r * 8) * NGATE + colb;
#pragma unroll
                    for (int gate = 0; gate < 4; gate++)
                        nG[gate][r] = __ldg((const float2*)&g_G[gb + gate * HID]);
                }
            }

            uint32_t afr[4];
            afr[0] = __float_as_uint(f2tf32(av.x * em0));
            afr[1] = __float_as_uint(f2tf32(av.y * em1));
            afr[2] = __float_as_uint(f2tf32(av.z * em0));
            afr[3] = __float_as_uint(f2tf32(av.w * em1));

            const float* Bb = Bfrag + kb8 * 256;
            float4 bA = *(const float4*)&Bb[lane * 4];        // gates 0,1
            float4 bB = *(const float4*)&Bb[128 + lane * 4];  // gates 2,3
            uint32_t b0[2] = {__float_as_uint(bA.x), __float_as_uint(bA.y)};
            uint32_t b1[2] = {__float_as_uint(bA.z), __float_as_uint(bA.w)};
            uint32_t b2[2] = {__float_as_uint(bB.x), __float_as_uint(bB.y)};
            uint32_t b3[2] = {__float_as_uint(bB.z), __float_as_uint(bB.w)};
            mma_tf32(acc[0], afr, b0);
            mma_tf32(acc[1], afr, b1);
            mma_tf32(acc[2], afr, b2);
            mma_tf32(acc[3], afr, b3);
        }

        // epilogue: LSTM pointwise + state/output/frag writes
        float* fb = hF_out + ((size_t)warp * 128 + bx) * 128;
#pragma unroll
        for (int r = 0; r < 2; r++) {
            int row = rb + g + r * 8;
            float em = r ? em1 : em0;
            float2 cp = *(const float2*)&g_c[row * HID + colb];
            float iv0 = acc[0][2 * r]     + pG[0][r].x;
            float iv1 = acc[0][2 * r + 1] + pG[0][r].y;
            float fv0 = acc[1][2 * r]     + pG[1][r].x;
            float fv1 = acc[1][2 * r + 1] + pG[1][r].y;
            float ov0 = acc[2][2 * r]     + pG[2][r].x;
            float ov1 = acc[2][2 * r + 1] + pG[2][r].y;
            float gv0 = acc[3][2 * r]     + pG[3][r].x;
            float gv1 = acc[3][2 * r + 1] + pG[3][r].y;
            float cn0 = sigmoidf_fast(fv0) * (cp.x * em) + sigmoidf_fast(iv0) * tanhf_fast(gv0);
            float cn1 = sigmoidf_fast(fv1) * (cp.y * em) + sigmoidf_fast(iv1) * tanhf_fast(gv1);
            float hn0 = sigmoidf_fast(ov0) * tanhf_fast(cn0);
            float hn1 = sigmoidf_fast(ov1) * tanhf_fast(cn1);
            *(float2*)&g_c[row * HID + colb] = make_float2(cn0, cn1);
            *(float2*)&out_hs[((size_t)t * BATCH + row) * HID + colb] = make_float2(hn0, hn1);
            fb[off0 + r] = hn0;   // raw h into next-step fragment buffer
            fb[off1 + r] = hn1;
        }

        grid_sync((unsigned)t);

        em0 = nem0; em1 = nem1;
#pragma unroll
        for (int gate = 0; gate < 4; gate++) {
            pG[gate][0] = nG[gate][0];
            pG[gate][1] = nG[gate][1];
        }
    }
}

// ---------------- final state writeback ----------------
// c from g_c; final hidden = hs[T-1] (already in out).

__global__ void write_final(float* __restrict__ out) {
    int idx = blockIdx.x * blockDim.x + threadIdx.x;
    if (idx < BATCH * HID) {
        int b = idx / HID, j = idx % HID;
        size_t base = (size_t)T_STEPS * BATCH * HID;
        out[base + (size_t)b * 2 * HID + j] = g_c[idx];
        out[base + (size_t)b * 2 * HID + HID + j] =
            out[(size_t)(T_STEPS - 1) * BATCH * HID + (size_t)b * HID + j];
    }
}

// ---------------- launch ----------------

extern "C" void kernel_launch(void* const* d_in, const int* in_sizes, int n_in,
                              void* d_out, int out_size) {
    const float* x    = (const float*)d_in[0];  // [T,B,D]
    const float* mask = (const float*)d_in[1];  // [T,B,1]
    const float* csh  = (const float*)d_in[2];  // [B,2H]
    const float* Wx   = (const float*)d_in[3];  // [D,4H]
    const float* Wh   = (const float*)d_in[4];  // [H,4H]
    const float* bias = (const float*)d_in[5];  // [4H]
    float* out = (float*)d_out;

    cudaFuncSetAttribute(lstm_persistent,
                         cudaFuncAttributeMaxDynamicSharedMemorySize, LS_SMEM_BYTES);
    cudaFuncSetAttribute(pregemm,
                         cudaFuncAttributeMaxDynamicSharedMemorySize, PG_SMEM_BYTES);

    init_state<<<(BATCH * HID + 255) / 256, 256>>>(csh);

    prep_xA<<<dim3(DIN / 32, (T_STEPS * BATCH) / 128), 256>>>(x);
    prep_WxB<<<dim3(NGATE / 128, DIN / 32), 256>>>(Wx);

    pregemm<<<dim3(NGATE / 128, (T_STEPS * BATCH) / 128), 256, PG_SMEM_BYTES>>>(bias);

    lstm_persistent<<<NBLK, 256, LS_SMEM_BYTES>>>(mask, Wh, out);

    write_final<<<(BATCH * HID + 255) / 256, 256>>>(out);
}

// round 14
// speedup vs baseline: 2.1187x; 1.0515x over previous
#include <cuda_runtime.h>
#include <cstdint>

#define T_STEPS 256
#define BATCH   128
#define DIN     1024
#define HID     1024
#define NGATE   4096  // 4*HID
#define NBLK    128

// Scratch (device globals; no allocation allowed in kernel_launch).
__device__ float g_G[(size_t)T_STEPS * BATCH * NGATE];   // x@Wx + b (512 MB)
__device__ float g_xA[(size_t)T_STEPS * BATCH * DIN];    // x, tf32-rounded, A-fragment order (128 MB)
__device__ float g_WxB[(size_t)DIN * NGATE];             // Wx, tf32-rounded, B-fragment order (16 MB)
__device__ float g_hF[2][BATCH * HID];                   // h (raw fp32), A-FRAGMENT order, dbl-buffered
__device__ float g_c[BATCH * HID];                       // cell state
__device__ unsigned g_cnt;                               // barrier arrive counter
__device__ volatile unsigned g_gen;                      // barrier generation

// ---------------- helpers ----------------

__device__ __forceinline__ float f2tf32(float x) {
    uint32_t u;
    asm("cvt.rna.tf32.f32 %0, %1;" : "=r"(u) : "f"(x));
    return __uint_as_float(u);
}

__device__ __forceinline__ void mma_tf32(float c[4], const uint32_t a[4], const uint32_t b[2]) {
    asm volatile(
        "mma.sync.aligned.m16n8k8.row.col.f32.tf32.tf32.f32 "
        "{%0,%1,%2,%3}, {%4,%5,%6,%7}, {%8,%9}, {%0,%1,%2,%3};"
        : "+f"(c[0]), "+f"(c[1]), "+f"(c[2]), "+f"(c[3])
        : "r"(a[0]), "r"(a[1]), "r"(a[2]), "r"(a[3]), "r"(b[0]), "r"(b[1]));
}

__device__ __forceinline__ float sigmoidf_fast(float x) {
    x = fminf(fmaxf(x, -30.f), 30.f);
    return __fdividef(1.f, 1.f + __expf(-x));
}

__device__ __forceinline__ float tanhf_fast(float x) {
    x = fminf(fmaxf(x, -15.f), 15.f);
    float e = __expf(2.f * x);
    return __fdividef(e - 1.f, e + 1.f);
}

// Software grid barrier (R9-proven atomic-counter version).
__device__ __forceinline__ void grid_sync(unsigned step) {
    __syncthreads();
    if (threadIdx.x == 0) {
        __threadfence();
        unsigned a = atomicAdd(&g_cnt, 1u);
        if (a == gridDim.x - 1) {
            g_cnt = 0;
            __threadfence();
            g_gen = step + 1;
        } else {
            while (g_gen < step + 1) __nanosleep(32);
        }
        __threadfence();
    }
    __syncthreads();
}

// ---------------- init state + barrier ----------------
// Fragment index for h[row][k]:
//   warp=row/16, g=row%8, r=(row%16)/8, kb8=k/8, t4=k%4, s=(k%8)/4
//   float idx = ((warp*128 + kb8)*32 + g*4 + t4)*4 + (r + 2*s)

__global__ void init_state(const float* __restrict__ csh) {
    int idx = blockIdx.x * blockDim.x + threadIdx.x;
    if (idx == 0) { g_cnt = 0; g_gen = 0; }
    if (idx < BATCH * HID) {
        int row = idx / HID, k = idx % HID;
        g_c[idx] = csh[row * 2 * HID + k];                 // cell first
        float h0 = csh[row * 2 * HID + HID + k];           // hidden second
        int warp = row >> 4, g = row & 7, r = (row >> 3) & 1;
        int kb8 = k >> 3, t4 = k & 3, s = (k >> 2) & 1;
        g_hF[0][((warp * 128 + kb8) * 32 + g * 4 + t4) * 4 + r + 2 * s] = h0;
    }
}

// ---------------- prep: permute+round x and Wx into fragment tile order ----

__global__ void prep_xA(const float* __restrict__ x) {
    __shared__ float tl[128 * 33];
    int ki = blockIdx.x, mi = blockIdx.y;
    int tid = threadIdx.x;  // 256
    for (int i = 0; i < 16; i++) {
        int e = tid + i * 256, r = e >> 5, c = e & 31;
        tl[r * 33 + c] = x[(size_t)(mi * 128 + r) * DIN + ki * 32 + c];
    }
    __syncthreads();
    size_t base = ((size_t)mi * 32 + ki) << 12;  // *4096
    for (int i = 0; i < 4; i++) {
        int o = tid + i * 256;           // float4 index 0..1023
        int lane = o & 31, mt = (o >> 5) & 1, wm = (o >> 6) & 3, k8 = o >> 8;
        int g = lane >> 2, t4 = lane & 3;
        int r0 = wm * 32 + mt * 16 + g, r1 = r0 + 8;
        int ka = k8 * 8 + t4, kb = ka + 4;
        float4 v;
        v.x = f2tf32(tl[r0 * 33 + ka]);
        v.y = f2tf32(tl[r1 * 33 + ka]);
        v.z = f2tf32(tl[r0 * 33 + kb]);
        v.w = f2tf32(tl[r1 * 33 + kb]);
        ((float4*)(g_xA + base))[o] = v;
    }
}

__global__ void prep_WxB(const float* __restrict__ Wx) {
    __shared__ float tl[32 * 129];
    int ni = blockIdx.x, ki = blockIdx.y;
    int tid = threadIdx.x;  // 256
    for (int i = 0; i < 16; i++) {
        int e = tid + i * 256, r = e >> 7, c = e & 127;
        tl[r * 129 + c] = Wx[(size_t)(ki * 32 + r) * NGATE + ni * 128 + c];
    }
    __syncthreads();
    size_t base = ((size_t)ki * 32 + ni) << 12;
    for (int i = 0; i < 4; i++) {
        int o = tid + i * 256;
        int lane = o & 31, w = (o >> 5) & 3, wn = (o >> 7) & 1, k8 = o >> 8;
        int g = lane >> 2, t4 = lane & 3;
        int c0 = wn * 64 + (2 * w) * 8 + g, c1 = c0 + 8;
        int ka = k8 * 8 + t4, kb = ka + 4;
        float4 v;
        v.x = f2tf32(tl[ka * 129 + c0]);
        v.y = f2tf32(tl[kb * 129 + c0]);
        v.z = f2tf32(tl[ka * 129 + c1]);
        v.w = f2tf32(tl[kb * 129 + c1]);
        ((float4*)(g_WxB + base))[o] = v;
    }
}

// ---------------- pre-GEMM: G = x @ Wx + bias ----------------
// Direct fragment streaming: both operands read straight from fragment-ordered
// global arrays via coalesced LDG.128 (6 per lane per k8; 512B/warp lines),
// double-buffered one chunk ahead. No smem, no syncs.

__global__ __launch_bounds__(256) void pregemm(const float* __restrict__ bias) {
    const int tid  = threadIdx.x;
    const int warp = tid >> 5, lane = tid & 31;
    const int g  = lane >> 2, t4 = lane & 3;
    const int wm = warp >> 1, wn = warp & 1;
    const int ni = blockIdx.x, mi = blockIdx.y;
    const int m0 = mi * 128, n0 = ni * 128;

    // A f4 for chunk kk: mi*32768 + kk*256 + wm*64 + mt*32 + lane
    const float4* ApL = (const float4*)g_xA + ((size_t)mi << 15) + wm * 64 + lane;
    // B f4 for chunk kk: ni*1024 + (kk>>2)*32768 + (kk&3)*256 + wn*128 + w*32 + lane
    const float4* BpL = (const float4*)g_WxB + ((size_t)ni << 10) + wn * 128 + lane;

    float acc[2][8][4];
#pragma unroll
    for (int a = 0; a < 2; a++)
#pragma unroll
        for (int b = 0; b < 8; b++)
#pragma unroll
            for (int c = 0; c < 4; c++) acc[a][b][c] = 0.f;

    float4 abuf[2][2], bbuf[2][4];
    // preload chunk 0
    abuf[0][0] = __ldg(ApL);
    abuf[0][1] = __ldg(ApL + 32);
#pragma unroll
    for (int w = 0; w < 4; w++) bbuf[0][w] = __ldg(BpL + w * 32);

#pragma unroll 2
    for (int kk = 0; kk < 128; kk++) {
        const int cur = kk & 1, nxt = cur ^ 1;
        if (kk < 127) {
            const int k2 = kk + 1;
            const float4* ap = ApL + (size_t)k2 * 256;
            abuf[nxt][0] = __ldg(ap);
            abuf[nxt][1] = __ldg(ap + 32);
            const float4* bp = BpL + ((size_t)(k2 >> 2) << 15) + (k2 & 3) * 256;
#pragma unroll
            for (int w = 0; w < 4; w++) bbuf[nxt][w] = __ldg(bp + w * 32);
        }
        uint32_t a0[4] = {__float_as_uint(abuf[cur][0].x), __float_as_uint(abuf[cur][0].y),
                          __float_as_uint(abuf[cur][0].z), __float_as_uint(abuf[cur][0].w)};
        uint32_t a1[4] = {__float_as_uint(abuf[cur][1].x), __float_as_uint(abuf[cur][1].y),
                          __float_as_uint(abuf[cur][1].z), __float_as_uint(abuf[cur][1].w)};
#pragma unroll
        for (int w = 0; w < 4; w++) {
            float4 fb = bbuf[cur][w];
            uint32_t b0[2] = {__float_as_uint(fb.x), __float_as_uint(fb.y)};
            uint32_t b1[2] = {__float_as_uint(fb.z), __float_as_uint(fb.w)};
            mma_tf32(acc[0][2 * w],     a0, b0);
            mma_tf32(acc[1][2 * w],     a1, b0);
            mma_tf32(acc[0][2 * w + 1], a0, b1);
            mma_tf32(acc[1][2 * w + 1], a1, b1);
        }
    }

#pragma unroll
    for (int mt = 0; mt < 2; mt++) {
#pragma unroll
        for (int nt = 0; nt < 8; nt++) {
            int r = m0 + wm * 32 + mt * 16 + g;
            int c = n0 + wn * 64 + nt * 8 + 2 * t4;
            float b0 = bias[c], b1 = bias[c + 1];
            float2 v0 = make_float2(acc[mt][nt][0] + b0, acc[mt][nt][1] + b1);
            float2 v1 = make_float2(acc[mt][nt][2] + b0, acc[mt][nt][3] + b1);
            *(float2*)&g_G[(size_t)r * NGATE + c]       = v0;
            *(float2*)&g_G[(size_t)(r + 8) * NGATE + c] = v1;
        }
    }
}

// ---------------- persistent recurrence (R13 best-passing, verbatim) ----------------
// 128 blocks, 256 threads (8 warps). Block b owns gate-columns [8b,8b+8).
// A fragments read DIRECTLY from g_hF (fragment-ordered, 1 coalesced LDG.128
// per lane per kb8, ring-16 prefetch). Mask applied at frag load. Epilogue
// writes raw h into next buffer's kb8=blockIdx slice.

#define BFRAG_FLOATS 32768       // 128 kblocks * 256 (Wh, resident)
#define LS_SMEM_BYTES (BFRAG_FLOATS * 4)  // 128 KB
#define RING 16

__global__ __launch_bounds__(256, 1) void lstm_persistent(
        const float* __restrict__ mask,
        const float* __restrict__ Wh,
        float* __restrict__ out_hs) {
    extern __shared__ float smem[];
    float* Bfrag = smem;

    const int tid  = threadIdx.x;
    const int warp = tid >> 5, lane = tid & 31;
    const int g  = lane >> 2, t4 = lane & 3;
    const int bx = blockIdx.x;
    const int j0 = bx * 8;
    const int rb = warp * 16;
    const int colb = j0 + 2 * t4;

    // epilogue fragment-store offsets (within this warp's kb8=bx tile)
    const int krel0 = 2 * t4, krel1 = 2 * t4 + 1;
    const int off0 = (g * 4 + (krel0 & 3)) * 4 + 2 * ((krel0 >> 2) & 1);
    const int off1 = (g * 4 + (krel1 & 3)) * 4 + 2 * ((krel1 >> 2) & 1);

    // ---- preload Wh fragments (once per launch) ----
    for (int idx = tid; idx < BFRAG_FLOATS; idx += 256) {
        int kb     = idx >> 8;
        int within = idx & 255;
        int q      = within >> 7;
        int rest   = within & 127;
        int lane_i = rest >> 2;
        int sub    = rest & 3;
        int gate   = q * 2 + (sub >> 1);
        int s      = sub & 1;
        int g8     = lane_i >> 2;
        int t4v    = lane_i & 3;
        int k      = kb * 8 + s * 4 + t4v;
        Bfrag[idx] = f2tf32(Wh[(size_t)k * NGATE + gate * HID + j0 + g8]);
    }
    __syncthreads();

    // per-step scalars for step 0
    float em0, em1;
    float2 pG[4][2];
    {
        em0 = 1.0f - __ldg(&mask[rb + g]);
        em1 = 1.0f - __ldg(&mask[rb + g + 8]);
#pragma unroll
        for (int r = 0; r < 2; r++) {
            size_t gb = ((size_t)(rb + g + r * 8)) * NGATE + colb;
#pragma unroll
            for (int gate = 0; gate < 4; gate++)
                pG[gate][r] = __ldg((const float2*)&g_G[gb + gate * HID]);
        }
    }

    for (int t = 0; t < T_STEPS; t++) {
        const float* __restrict__ hF_in = g_hF[t & 1] + (size_t)warp * 16384;
        float*       __restrict__ hF_out = g_hF[(t + 1) & 1];

        float nem0 = 0.f, nem1 = 0.f;
        float2 nG[4][2];
#pragma unroll
        for (int gate = 0; gate < 4; gate++) {
            nG[gate][0] = make_float2(0.f, 0.f);
            nG[gate][1] = make_float2(0.f, 0.f);
        }

        float acc[4][4];
#pragma unroll
        for (int a = 0; a < 4; a++)
#pragma unroll
            for (int c = 0; c < 4; c++) acc[a][c] = 0.f;

        // ring prologue: 16 outstanding coalesced LDG.128
        float4 ring[RING];
#pragma unroll
        for (int p = 0; p < RING; p++)
            ring[p] = *(const float4*)&hF_in[p * 128 + lane * 4];

#pragma unroll 16
        for (int kb8 = 0; kb8 < 128; kb8++) {
            float4 av = ring[kb8 & (RING - 1)];
            if (kb8 < 128 - RING)
                ring[kb8 & (RING - 1)] =
                    *(const float4*)&hF_in[(kb8 + RING) * 128 + lane * 4];

            if (kb8 == 64 && t + 1 < T_STEPS) {
                const float* nmrow = mask + (size_t)(t + 1) * BATCH;
                nem0 = 1.0f - __ldg(&nmrow[rb + g]);
                nem1 = 1.0f - __ldg(&nmrow[rb + g + 8]);
#pragma unroll
                for (int r = 0; r < 2; r++) {
                    size_t gb = ((size_t)(t + 1) * BATCH + rb + g + r * 8) * NGATE + colb;
#pragma unroll
                    for (int gate = 0; gate < 4; gate++)
                        nG[gate][r] = __ldg((const float2*)&g_G[gb + gate * HID]);
                }
            }

            uint32_t afr[4];
            afr[0] = __float_as_uint(f2tf32(av.x * em0));
            afr[1] = __float_as_uint(f2tf32(av.y * em1));
            afr[2] = __float_as_uint(f2tf32(av.z * em0));
            afr[3] = __float_as_uint(f2tf32(av.w * em1));

            const float* Bb = Bfrag + kb8 * 256;
            float4 bA = *(const float4*)&Bb[lane * 4];        // gates 0,1
            float4 bB = *(const float4*)&Bb[128 + lane * 4];  // gates 2,3
            uint32_t b0[2] = {__float_as_uint(bA.x), __float_as_uint(bA.y)};
            uint32_t b1[2] = {__float_as_uint(bA.z), __float_as_uint(bA.w)};
            uint32_t b2[2] = {__float_as_uint(bB.x), __float_as_uint(bB.y)};
            uint32_t b3[2] = {__float_as_uint(bB.z), __float_as_uint(bB.w)};
            mma_tf32(acc[0], afr, b0);
            mma_tf32(acc[1], afr, b1);
            mma_tf32(acc[2], afr, b2);
            mma_tf32(acc[3], afr, b3);
        }

        // epilogue: LSTM pointwise + state/output/frag writes
        float* fb = hF_out + ((size_t)warp * 128 + bx) * 128;
#pragma unroll
        for (int r = 0; r < 2; r++) {
            int row = rb + g + r * 8;
            float em = r ? em1 : em0;
            float2 cp = *(const float2*)&g_c[row * HID + colb];
            float iv0 = acc[0][2 * r]     + pG[0][r].x;
            float iv1 = acc[0][2 * r + 1] + pG[0][r].y;
            float fv0 = acc[1][2 * r]     + pG[1][r].x;
            float fv1 = acc[1][2 * r + 1] + pG[1][r].y;
            float ov0 = acc[2][2 * r]     + pG[2][r].x;
            float ov1 = acc[2][2 * r + 1] + pG[2][r].y;
            float gv0 = acc[3][2 * r]     + pG[3][r].x;
            float gv1 = acc[3][2 * r + 1] + pG[3][r].y;
            float cn0 = sigmoidf_fast(fv0) * (cp.x * em) + sigmoidf_fast(iv0) * tanhf_fast(gv0);
            float cn1 = sigmoidf_fast(fv1) * (cp.y * em) + sigmoidf_fast(iv1) * tanhf_fast(gv1);
            float hn0 = sigmoidf_fast(ov0) * tanhf_fast(cn0);
            float hn1 = sigmoidf_fast(ov1) * tanhf_fast(cn1);
            *(float2*)&g_c[row * HID + colb] = make_float2(cn0, cn1);
            *(float2*)&out_hs[((size_t)t * BATCH + row) * HID + colb] = make_float2(hn0, hn1);
            fb[off0 + r] = hn0;   // raw h into next-step fragment buffer
            fb[off1 + r] = hn1;
        }

        grid_sync((unsigned)t);

        em0 = nem0; em1 = nem1;
#pragma unroll
        for (int gate = 0; gate < 4; gate++) {
            pG[gate][0] = nG[gate][0];
            pG[gate][1] = nG[gate][1];
        }
    }
}

// ---------------- final state writeback ----------------
// c from g_c; final hidden = hs[T-1] (already in out).

__global__ void write_final(float* __restrict__ out) {
    int idx = blockIdx.x * blockDim.x + threadIdx.x;
    if (idx < BATCH * HID) {
        int b = idx / HID, j = idx % HID;
        size_t base = (size_t)T_STEPS * BATCH * HID;
        out[base + (size_t)b * 2 * HID + j] = g_c[idx];
        out[base + (size_t)b * 2 * HID + HID + j] =
            out[(size_t)(T_STEPS - 1) * BATCH * HID + (size_t)b * HID + j];
    }
}

// ---------------- launch ----------------

extern "C" void kernel_launch(void* const* d_in, const int* in_sizes, int n_in,
                              void* d_out, int out_size) {
    const float* x    = (const float*)d_in[0];  // [T,B,D]
    const float* mask = (const float*)d_in[1];  // [T,B,1]
    const float* csh  = (const float*)d_in[2];  // [B,2H]
    const float* Wx   = (const float*)d_in[3];  // [D,4H]
    const float* Wh   = (const float*)d_in[4];  // [H,4H]
    const float* bias = (const float*)d_in[5];  // [4H]
    float* out = (float*)d_out;

    cudaFuncSetAttribute(lstm_persistent,
                         cudaFuncAttributeMaxDynamicSharedMemorySize, LS_SMEM_BYTES);

    init_state<<<(BATCH * HID + 255) / 256, 256>>>(csh);

    prep_xA<<<dim3(DIN / 32, (T_STEPS * BATCH) / 128), 256>>>(x);
    prep_WxB<<<dim3(NGATE / 128, DIN / 32), 256>>>(Wx);

    pregemm<<<dim3(NGATE / 128, (T_STEPS * BATCH) / 128), 256>>>(bias);

    lstm_persistent<<<NBLK, 256, LS_SMEM_BYTES>>>(mask, Wh, out);

    write_final<<<(BATCH * HID + 255) / 256, 256>>>(out);
}